// round 15
// baseline (speedup 1.0000x reference)
#include <cuda_runtime.h>
#include <cstdint>

#define NB   32      // batch
#define SS   400     // src len
#define TDD  30      // trg len
#define EE   256     // embed
#define HH   512     // HE == HD == 512
#define G3   1536    // 3*H
#define VV   50000
#define OOVV 50
#define VO   50050

#define CDIV(a,b) (((a)+(b)-1)/(b))

// ---------------- scratch (device globals; no allocations allowed) ----------------
__device__ float g_Xsrc[SS * NB * EE];
__device__ float g_Xtrg[TDD * NB * EE];
__device__ float g_Gf[(size_t)SS * NB * G3];    // transposed: [s][col 1536][n 32]
__device__ float g_Gb[(size_t)SS * NB * G3];
__device__ float g_Gd[(size_t)TDD * NB * G3];
__device__ float g_enc[(size_t)NB * SS * 2 * HH];
__device__ float g_KP[(size_t)NB * SS * HH];
__device__ float g_Ht[2 * 2 * HH * NB];         // encoder h: [parity][dir][k/4][n][4]
__device__ float g_Ht2[2 * 2 * HH * NB];        // decoder h (separate: runs concurrently)
__device__ float g_Hdec[TDD * NB * HH];
__device__ float g_Q[TDD * NB * HH];
__device__ float g_ATTN[TDD * NB * SS];
__device__ float g_CTX[TDD * NB * 2 * HH];
__device__ float g_CONC[TDD * NB * G3];
__device__ float g_GEN1[TDD * NB * HH];
__device__ float g_LOG[(size_t)TDD * NB * VV];
__device__ float g_pg[TDD * NB];
__device__ float g_inv[TDD * NB];
__device__ float g_mx[TDD * NB];
__device__ int   g_ctr[1024];   // enc fwd [0..399], enc bwd [400..799], dec [830..859]

// ---------------- helpers ----------------
__device__ __forceinline__ float fsigmoid(float x) { return 1.f / (1.f + __expf(-x)); }
__device__ __forceinline__ float ftanh(float x) {           // exact-ish (GRU recurrence)
    x = fminf(fmaxf(x, -15.f), 15.f);
    float e2 = __expf(2.f * x);
    return (e2 - 1.f) / (e2 + 1.f);
}
__device__ __forceinline__ float htanh(float x) {           // HW MUFU tanh (attention only)
    float y;
    asm("tanh.approx.f32 %0, %1;" : "=f"(y) : "f"(x));
    return y;
}
__device__ __forceinline__ uint32_t f2tf(float x) {
    uint32_t u;
    asm("cvt.rna.tf32.f32 %0, %1;" : "=r"(u) : "f"(x));
    return u;
}
__device__ __forceinline__ void cpa16(uint32_t dst, const void* src, int sz) {
    asm volatile("cp.async.cg.shared.global [%0], [%1], 16, %2;"
                 :: "r"(dst), "l"(src), "r"(sz) : "memory");
}

// ---------------- embedding gather ------------------------------------------------
__global__ void gather_kernel(const int* __restrict__ ids, const float* __restrict__ embed,
                              float* __restrict__ X, int S)
{
    int row = blockIdx.x;                 // s*32 + n
    int s = row >> 5, n = row & 31;
    int id = ids[n * S + s];
    X[(size_t)row * EE + threadIdx.x] = embed[(size_t)id * EE + threadIdx.x];
}

// ---------------- tf32 tensor-core GEMM v3: cp.async 3-stage ----------------------
__global__ __launch_bounds__(256, 2) void gemm_tf32(
    const float* __restrict__ A, const float* __restrict__ B,
    const float* __restrict__ bias, float* __restrict__ C,
    int M, int N, int K, int transB, int gmode)
{
    extern __shared__ float sm[];        // 3 stages x (A 2560 + B 2560) floats
    const int bm = blockIdx.x * 128;
    const int bn = blockIdx.y * 128;
    const int tid = threadIdx.x;
    const int lane = tid & 31;
    const int warp = tid >> 5;
    const int wm = warp & 1, wn = warp >> 1;
    const uint32_t smBase = (uint32_t)__cvta_generic_to_shared(sm);

    float acc[4][4][4];
#pragma unroll
    for (int mi = 0; mi < 4; mi++)
#pragma unroll
        for (int ni = 0; ni < 4; ni++)
#pragma unroll
            for (int q = 0; q < 4; q++) acc[mi][ni][q] = 0.f;

    const int KT = K >> 4;

    auto issue = [&](int st, int k0) {   // st MUST be a stage index 0..2
        const uint32_t AsU = smBase + (uint32_t)st * 5120u * 4u;
        const uint32_t BsU = AsU + 2560u * 4u;
#pragma unroll
        for (int c = 0; c < 2; c++) {
            int idx = c * 256 + tid;
            int row = idx >> 2, cq = idx & 3;
            const float* src = A + (size_t)(bm + row) * K + k0 + cq * 4;
            int sz = (bm + row < M) ? 16 : 0;
            if (!sz) src = A;
            cpa16(AsU + (uint32_t)(row * 20 + cq * 4) * 4u, src, sz);
        }
        if (!transB) {
#pragma unroll
            for (int c = 0; c < 2; c++) {
                int idx = c * 256 + tid;
                int row = idx >> 5, cq = idx & 31;
                int col = bn + cq * 4;
                const float* src = B + (size_t)(k0 + row) * N + col;
                int rem = N - col;
                int sz = rem >= 4 ? 16 : (rem > 0 ? rem * 4 : 0);
                if (!sz) src = B;
                cpa16(BsU + (uint32_t)(row * 136 + cq * 4) * 4u, src, sz);
            }
        } else {
#pragma unroll
            for (int c = 0; c < 2; c++) {
                int idx = c * 256 + tid;
                int row = idx >> 2, cq = idx & 3;
                const float* src = B + (size_t)(bn + row) * K + k0 + cq * 4;
                int sz = (bn + row < N) ? 16 : 0;
                if (!sz) src = B;
                cpa16(BsU + (uint32_t)(row * 20 + cq * 4) * 4u, src, sz);
            }
        }
        asm volatile("cp.async.commit_group;" ::: "memory");
    };

    issue(0, 0);
    if (KT > 1) issue(1, 16);
    else asm volatile("cp.async.commit_group;" ::: "memory");

    for (int kt = 0; kt < KT; kt++) {
        const int st = kt % 3;
        asm volatile("cp.async.wait_group 1;" ::: "memory");
        __syncthreads();
        const uint32_t* As = reinterpret_cast<const uint32_t*>(sm + st * 5120);
        const uint32_t* Bs = As + 2560;
#pragma unroll
        for (int ks = 0; ks < 2; ks++) {
            uint32_t af[4][4], bf[4][2];
            const int r0 = wm * 64 + (lane >> 2);
            const int c0 = ks * 8 + (lane & 3);
#pragma unroll
            for (int mi = 0; mi < 4; mi++) {
                const int rr = r0 + mi * 16;
                af[mi][0] = As[rr * 20 + c0];
                af[mi][1] = As[(rr + 8) * 20 + c0];
                af[mi][2] = As[rr * 20 + c0 + 4];
                af[mi][3] = As[(rr + 8) * 20 + c0 + 4];
            }
#pragma unroll
            for (int ni = 0; ni < 4; ni++) {
                const int nn = wn * 32 + ni * 8 + (lane >> 2);
                if (transB) {
                    bf[ni][0] = Bs[nn * 20 + c0];
                    bf[ni][1] = Bs[nn * 20 + c0 + 4];
                } else {
                    bf[ni][0] = Bs[c0 * 136 + nn];
                    bf[ni][1] = Bs[(c0 + 4) * 136 + nn];
                }
            }
#pragma unroll
            for (int mi = 0; mi < 4; mi++)
#pragma unroll
                for (int ni = 0; ni < 4; ni++)
                    asm volatile(
                        "mma.sync.aligned.m16n8k8.row.col.f32.tf32.tf32.f32 "
                        "{%0,%1,%2,%3}, {%4,%5,%6,%7}, {%8,%9}, {%0,%1,%2,%3};"
                        : "+f"(acc[mi][ni][0]), "+f"(acc[mi][ni][1]),
                          "+f"(acc[mi][ni][2]), "+f"(acc[mi][ni][3])
                        : "r"(af[mi][0]), "r"(af[mi][1]), "r"(af[mi][2]), "r"(af[mi][3]),
                          "r"(bf[ni][0]), "r"(bf[ni][1]));
        }
        if (kt + 2 < KT) issue((kt + 2) % 3, (kt + 2) << 4);
        else asm volatile("cp.async.commit_group;" ::: "memory");
    }

#pragma unroll
    for (int mi = 0; mi < 4; mi++) {
#pragma unroll
        for (int ni = 0; ni < 4; ni++) {
            const int row = bm + wm * 64 + mi * 16 + (lane >> 2);
            const int col = bn + wn * 32 + ni * 8 + (lane & 3) * 2;
#pragma unroll
            for (int h = 0; h < 2; h++) {
                const int m = row + h * 8;
                if (m < M) {
#pragma unroll
                    for (int q = 0; q < 2; q++) {
                        const int n = col + q;
                        if (n < N) {
                            float v = acc[mi][ni][h * 2 + q];
                            if (bias) v += __ldg(&bias[n]);
                            if (gmode) C[((size_t)(m >> 5) * N + n) * 32 + (m & 31)] = v;
                            else       C[(size_t)m * N + n] = v;
                        }
                    }
                }
            }
        }
    }
}

// ---------------- persistent GRU recurrence v3 (tensor-core, 512 threads) ---------
// 32 CTAs per direction; each CTA owns 16 hidden units (48 gate-rows = 3 m16 tiles,
// no padding) x 32 batch, K=512 split over 16 warps (32 each). All 16 warps do the
// gate phase (one unit each). Narrower 32-CTA grid barrier per direction.
__global__ __launch_bounds__(512, 1) void gru_persist(
    const float* __restrict__ G0T, const float* __restrict__ G1T,
    const float* __restrict__ Whh0, const float* __restrict__ Whh1,
    const float* __restrict__ bhh0, const float* __restrict__ bhh1,
    float* __restrict__ Ht, int* ctr,
    float* __restrict__ encOut, float* __restrict__ hdecOut,
    int nSteps, int nCTA, int encMode)
{
    extern __shared__ uint32_t smemU[];
    uint32_t* AF = smemU;                              // [16 warps][12 (mi*4+ki)][32 lanes][4]
    float* rs = reinterpret_cast<float*>(smemU + 16 * 12 * 32 * 4);  // [16*48 rows][33]

    const int dir   = encMode ? (blockIdx.x >> 5) : 0;
    const int utile = blockIdx.x & 31;
    const int u0 = utile * 16;
    const float* Whh = dir ? Whh1 : Whh0;
    const float* bhh = dir ? bhh1 : bhh0;
    const float* GT  = dir ? G1T  : G0T;

    const int tid = threadIdx.x, lane = tid & 31, wk = tid >> 5;   // wk 0..15

    // ---- pre-swizzle A (Whh gate-rows 0..47) into fragment order, tf32, once ----
#pragma unroll
    for (int mi = 0; mi < 3; mi++)
#pragma unroll
        for (int ki = 0; ki < 4; ki++)
#pragma unroll
            for (int r = 0; r < 4; r++) {
                int row = mi * 16 + (lane >> 2) + (r & 1) * 8;           // gate-row 0..47
                int col = wk * 32 + ki * 8 + (lane & 3) + (r >> 1) * 4;  // k
                int g = row >> 4, uu = row & 15;
                float v = Whh[((size_t)(g * 512 + u0 + uu)) * 512 + col];
                AF[((wk * 12 + mi * 4 + ki) * 32 + lane) * 4 + r] = f2tf(v);
            }
    const int u = u0 + wk;               // every warp owns a unit now
    const float b_r = bhh[u];
    const float b_z = bhh[512 + u];
    const float b_n = bhh[1024 + u];
    __syncthreads();

    float hprev = 0.f;

    for (int t = 0; t < nSteps; t++) {
        const int p = t & 1;
        const float* Hp = Ht + ((size_t)p * 2 + dir) * HH * NB;
        float*       Hn = Ht + ((size_t)(1 - p) * 2 + dir) * HH * NB;
        const int gidx = dir ? (nSteps - 1 - t) : t;
        const float* Gt = GT + (size_t)gidx * G3 * NB;

        float gir = __ldg(&Gt[u * 32 + lane]);
        float giz = __ldg(&Gt[(512 + u) * 32 + lane]);
        float gin = __ldg(&Gt[(1024 + u) * 32 + lane]);

        // ---- B fragments: coalesced 128B loads from packed Ht ----
        uint32_t bReg[4][4][2];          // [ni][ki][2]
        const int kq = wk * 8;
#pragma unroll
        for (int ki = 0; ki < 4; ki++)
#pragma unroll
            for (int ni = 0; ni < 4; ni++) {
                float v0 = __ldcg(&Hp[(kq + ki * 2) * 128 + ni * 32 + lane]);
                float v1 = __ldcg(&Hp[(kq + ki * 2 + 1) * 128 + ni * 32 + lane]);
                bReg[ni][ki][0] = f2tf(v0);
                bReg[ni][ki][1] = f2tf(v1);
            }

        float acc[3][4][4];
#pragma unroll
        for (int mi = 0; mi < 3; mi++)
#pragma unroll
            for (int ni = 0; ni < 4; ni++)
#pragma unroll
                for (int q = 0; q < 4; q++) acc[mi][ni][q] = 0.f;

#pragma unroll
        for (int mi = 0; mi < 3; mi++)
#pragma unroll
            for (int ki = 0; ki < 4; ki++) {
                uint4 a = *reinterpret_cast<const uint4*>(
                    &AF[((wk * 12 + mi * 4 + ki) * 32 + lane) * 4]);
#pragma unroll
                for (int ni = 0; ni < 4; ni++)
                    asm volatile(
                        "mma.sync.aligned.m16n8k8.row.col.f32.tf32.tf32.f32 "
                        "{%0,%1,%2,%3}, {%4,%5,%6,%7}, {%8,%9}, {%0,%1,%2,%3};"
                        : "+f"(acc[mi][ni][0]), "+f"(acc[mi][ni][1]),
                          "+f"(acc[mi][ni][2]), "+f"(acc[mi][ni][3])
                        : "r"(a.x), "r"(a.y), "r"(a.z), "r"(a.w),
                          "r"(bReg[ni][ki][0]), "r"(bReg[ni][ki][1]));
            }

        // ---- store K-partials to SMEM (stride 33) ----
        {
            const int row0 = lane >> 2, col0 = 2 * (lane & 3);
#pragma unroll
            for (int mi = 0; mi < 3; mi++)
#pragma unroll
                for (int ni = 0; ni < 4; ni++) {
                    float* base = &rs[(wk * 48 + mi * 16 + row0) * 33 + ni * 8 + col0];
                    base[0]          = acc[mi][ni][0];
                    base[1]          = acc[mi][ni][1];
                    base[33 * 8]     = acc[mi][ni][2];
                    base[33 * 8 + 1] = acc[mi][ni][3];
                }
        }
        __syncthreads();

        // ---- gate phase: every warp owns unit u = u0+wk, lane = n ----
        {
            float ar = 0.f, az = 0.f, an = 0.f;
#pragma unroll
            for (int w2 = 0; w2 < 16; w2++) {
                ar += rs[(w2 * 48 + wk) * 33 + lane];
                az += rs[(w2 * 48 + 16 + wk) * 33 + lane];
                an += rs[(w2 * 48 + 32 + wk) * 33 + lane];
            }
            float r = fsigmoid(gir + ar + b_r);
            float z = fsigmoid(giz + az + b_z);
            float nn = ftanh(gin + (an + b_n) * r);
            float hnew = (1.f - z) * nn + z * hprev;
            hprev = hnew;
            __stcg(&Hn[(u >> 2) * 128 + lane * 4 + (u & 3)], hnew);
            if (encMode) {
                int s = dir ? (nSteps - 1 - t) : t;
                encOut[(size_t)lane * SS * 1024 + (size_t)s * 1024 + dir * 512 + u] = hnew;
            } else {
                hdecOut[(size_t)t * NB * HH + (size_t)lane * HH + u] = hnew;
            }
        }
        __syncthreads();

        if (t + 1 < nSteps) {
            if (tid == 0) {
                int* a = &ctr[dir ? (nSteps + t) : t];
                asm volatile("red.release.gpu.global.add.u32 [%0], 1;" :: "l"(a) : "memory");
                unsigned v;
                do {
                    asm volatile("ld.acquire.gpu.global.u32 %0, [%1];" : "=r"(v) : "l"(a) : "memory");
                } while (v < (unsigned)nCTA);
            }
            __syncthreads();
        }
    }
}

// ---------------- attention scores + softmax (one CTA per (t,n) row) --------------
__global__ void score_kernel(const float* __restrict__ Q, const float* __restrict__ KP,
                             const float* __restrict__ mask, const float* __restrict__ vvec,
                             float* __restrict__ ATTN)
{
    const int row = blockIdx.x;          // t*32 + n
    const int n = row & 31;
    const int tid = threadIdx.x, lane = tid & 31, warp = tid >> 5;
    __shared__ float qs[HH], vs[HH], es[SS], red[256];

    for (int i = tid; i < HH; i += 256) { qs[i] = Q[(size_t)row * HH + i]; vs[i] = vvec[i]; }
    __syncthreads();

    for (int s = warp; s < SS; s += 8) {
        const float* kp = KP + ((size_t)n * SS + s) * HH;
        float part = 0.f;
        for (int d = lane; d < HH; d += 32)
            part += htanh(kp[d] + qs[d]) * vs[d];
#pragma unroll
        for (int o = 16; o; o >>= 1) part += __shfl_xor_sync(0xffffffffu, part, o);
        if (lane == 0) es[s] = part + (1.f - mask[n * SS + s]) * (-1e10f);
    }
    __syncthreads();

    float m = -1e30f;
    for (int s = tid; s < SS; s += 256) m = fmaxf(m, es[s]);
    red[tid] = m; __syncthreads();
    for (int st = 128; st; st >>= 1) { if (tid < st) red[tid] = fmaxf(red[tid], red[tid + st]); __syncthreads(); }
    float mx = red[0]; __syncthreads();

    float sum = 0.f;
    for (int s = tid; s < SS; s += 256) { float e = __expf(es[s] - mx); es[s] = e; sum += e; }
    red[tid] = sum; __syncthreads();
    for (int st = 128; st; st >>= 1) { if (tid < st) red[tid] += red[tid + st]; __syncthreads(); }
    float inv = 1.f / red[0]; __syncthreads();

    for (int s = tid; s < SS; s += 256)
        ATTN[(size_t)row * SS + s] = es[s] * inv;
}

// ---------------- context: CTX[t,n,:] = sum_s ATTN[t,n,s] * enc[n,s,:] ------------
__global__ __launch_bounds__(256) void ctx_kernel(
    const float* __restrict__ ATTN, const float* __restrict__ ENC,
    float* __restrict__ CTX)
{
    const int n = blockIdx.y;
    const int d = blockIdx.x * 256 + threadIdx.x;
    const int tid = threadIdx.x;
    __shared__ float at[TDD][129];

    float acc[TDD];
#pragma unroll
    for (int t = 0; t < TDD; t++) acc[t] = 0.f;

    for (int s0 = 0; s0 < SS; s0 += 128) {
        __syncthreads();
        for (int idx = tid; idx < TDD * 128; idx += 256) {
            int t = idx >> 7, si = idx & 127;
            at[t][si] = (s0 + si < SS) ? ATTN[((size_t)(t * NB + n)) * SS + s0 + si] : 0.f;
        }
        __syncthreads();
        const int lim = min(128, SS - s0);
        for (int si = 0; si < lim; si++) {
            float e = __ldg(&ENC[((size_t)n * SS + s0 + si) * 1024 + d]);
#pragma unroll
            for (int t = 0; t < TDD; t++) acc[t] = fmaf(at[t][si], e, acc[t]);
        }
    }
#pragma unroll
    for (int t = 0; t < TDD; t++)
        CTX[((size_t)(t * NB + n)) * 1024 + d] = acc[t];
}

// ---------------- concat [h, ctx] --------------------------------------------------
__global__ void concat_kernel(const float* __restrict__ H, const float* __restrict__ CTX,
                              float* __restrict__ C)
{
    int row = blockIdx.x;
    for (int i = threadIdx.x; i < G3; i += 256)
        C[(size_t)row * G3 + i] = (i < HH) ? H[(size_t)row * HH + i]
                                           : CTX[(size_t)row * 1024 + (i - HH)];
}

// ---------------- row softmax stats over V: mx + 1/sum (no exp write) -------------
__global__ void softmax_kernel(const float* __restrict__ LOG, float* __restrict__ mxv,
                               float* __restrict__ invs)
{
    const int row = blockIdx.x, tid = threadIdx.x;
    const float* p = LOG + (size_t)row * VV;
    __shared__ float red[256];
    float m = -1e30f;
    for (int i = tid; i < VV; i += 256) m = fmaxf(m, p[i]);
    red[tid] = m; __syncthreads();
    for (int st = 128; st; st >>= 1) { if (tid < st) red[tid] = fmaxf(red[tid], red[tid + st]); __syncthreads(); }
    float mx = red[0]; __syncthreads();
    float sum = 0.f;
    for (int i = tid; i < VV; i += 256) sum += __expf(p[i] - mx);
    red[tid] = sum; __syncthreads();
    for (int st = 128; st; st >>= 1) { if (tid < st) red[tid] += red[tid + st]; __syncthreads(); }
    if (tid == 0) { mxv[row] = mx; invs[row] = 1.f / red[0]; }
}

// ---------------- p_gen = sigmoid([xi, ctx, h] @ Wp + bp) -------------------------
__global__ void pgen_kernel(const float* __restrict__ Xtrg, const float* __restrict__ CTX,
                            const float* __restrict__ H, const float* __restrict__ Wp,
                            const float* __restrict__ bp, float* __restrict__ pg)
{
    const int warp = threadIdx.x >> 5, lane = threadIdx.x & 31;
    const int row = blockIdx.x * 8 + warp;
    float part = 0.f;
    for (int k = lane; k < 1792; k += 32) {
        float xv;
        if (k < 256)       xv = Xtrg[(size_t)row * EE + k];
        else if (k < 1280) xv = CTX[(size_t)row * 1024 + (k - 256)];
        else               xv = H[(size_t)row * HH + (k - 1280)];
        part += xv * Wp[k];
    }
#pragma unroll
    for (int o = 16; o; o >>= 1) part += __shfl_xor_sync(0xffffffffu, part, o);
    if (lane == 0) pg[row] = fsigmoid(part + bp[0]);
}

// ---------------- out = p_gen * softmax(LOG) (exp recomputed; OOV zeroed) ---------
__global__ void outfill_kernel(const float* __restrict__ LOG, const float* __restrict__ pg,
                               const float* __restrict__ mxv, const float* __restrict__ invs,
                               float* __restrict__ out)
{
    const int row = blockIdx.y;          // t*32 + n
    const int t = row / NB, n = row % NB;
    const int vv = blockIdx.x * 256 + threadIdx.x;
    if (vv >= VO) return;
    float val = 0.f;
    if (vv < VV)
        val = pg[row] * invs[row] * __expf(LOG[(size_t)row * VV + vv] - mxv[row]);
    out[((size_t)n * TDD + t) * VO + vv] = val;
}

// ---------------- deterministic scatter-add of (1-p)*attn at ptr indices ----------
__global__ void scatter_kernel(const float* __restrict__ ATTN, const float* __restrict__ pg,
                               const int* __restrict__ ptr_idx, float* __restrict__ out)
{
    const int row = blockIdx.x;          // t*32 + n
    const int t = row / NB, n = row % NB;
    __shared__ int   sidx[SS];
    __shared__ float sw[SS];
    const int s = threadIdx.x;
    const float om = 1.f - pg[row];
    if (s < SS) {
        sidx[s] = ptr_idx[n * SS + s];
        sw[s]   = om * ATTN[(size_t)row * SS + s];
    }
    __syncthreads();
    if (s < SS) {
        int my = sidx[s];
        bool first = true;
        for (int s2 = 0; s2 < s; s2++) if (sidx[s2] == my) { first = false; break; }
        if (first) {
            float val = sw[s];
            for (int s2 = s + 1; s2 < SS; s2++) if (sidx[s2] == my) val += sw[s2];
            out[((size_t)n * TDD + t) * VO + my] += val;   // rows exclusive -> no atomics
        }
    }
}

// ---------------- launch --------------------------------------------------------
extern "C" void kernel_launch(void* const* d_in, const int* in_sizes, int n_in,
                              void* d_out, int out_size)
{
    const int*   src_ids  = (const int*)  d_in[0];
    const float* src_mask = (const float*)d_in[1];
    const int*   trg_ids  = (const int*)  d_in[2];
    const int*   ptr_idx  = (const int*)  d_in[3];
    const float* embed    = (const float*)d_in[4];
    const float* Wih_f = (const float*)d_in[5],  *Whh_f = (const float*)d_in[6];
    const float* bih_f = (const float*)d_in[7],  *bhh_f = (const float*)d_in[8];
    const float* Wih_b = (const float*)d_in[9],  *Whh_b = (const float*)d_in[10];
    const float* bih_b = (const float*)d_in[11], *bhh_b = (const float*)d_in[12];
    const float* Wih_d = (const float*)d_in[13], *Whh_d = (const float*)d_in[14];
    const float* bih_d = (const float*)d_in[15], *bhh_d = (const float*)d_in[16];
    const float* Wk    = (const float*)d_in[17], *Wd    = (const float*)d_in[18];
    const float* battn = (const float*)d_in[19], *vvec  = (const float*)d_in[20];
    const float* W1    = (const float*)d_in[21], *b1    = (const float*)d_in[22];
    const float* W2    = (const float*)d_in[23], *b2    = (const float*)d_in[24];
    const float* Wp    = (const float*)d_in[25], *bp    = (const float*)d_in[26];
    float* out = (float*)d_out;

    float *Xsrc, *Xtrg, *Gf, *Gb, *Gd, *enc, *KP, *Ht, *Ht2, *Hdec, *Q, *ATTN, *CTX,
          *CONC, *GEN1, *LOG, *pg, *invs, *mxv;
    int* ctr;
    cudaGetSymbolAddress((void**)&Xsrc, g_Xsrc);
    cudaGetSymbolAddress((void**)&Xtrg, g_Xtrg);
    cudaGetSymbolAddress((void**)&Gf,   g_Gf);
    cudaGetSymbolAddress((void**)&Gb,   g_Gb);
    cudaGetSymbolAddress((void**)&Gd,   g_Gd);
    cudaGetSymbolAddress((void**)&enc,  g_enc);
    cudaGetSymbolAddress((void**)&KP,   g_KP);
    cudaGetSymbolAddress((void**)&Ht,   g_Ht);
    cudaGetSymbolAddress((void**)&Ht2,  g_Ht2);
    cudaGetSymbolAddress((void**)&Hdec, g_Hdec);
    cudaGetSymbolAddress((void**)&Q,    g_Q);
    cudaGetSymbolAddress((void**)&ATTN, g_ATTN);
    cudaGetSymbolAddress((void**)&CTX,  g_CTX);
    cudaGetSymbolAddress((void**)&CONC, g_CONC);
    cudaGetSymbolAddress((void**)&GEN1, g_GEN1);
    cudaGetSymbolAddress((void**)&LOG,  g_LOG);
    cudaGetSymbolAddress((void**)&pg,   g_pg);
    cudaGetSymbolAddress((void**)&invs, g_inv);
    cudaGetSymbolAddress((void**)&mxv,  g_mx);
    cudaGetSymbolAddress((void**)&ctr,  g_ctr);

    // gru v3: AF 16*12*32*4 u32 (96KB) + rs 16*48*33 f32 (99KB) = 195KB
    const int persistSmem = (16 * 12 * 32 * 4) * 4 + (16 * 48 * 33) * 4;
    cudaFuncSetAttribute(gru_persist, cudaFuncAttributeMaxDynamicSharedMemorySize, persistSmem);
    const int gemmSmem = 3 * 5120 * 4;
    cudaFuncSetAttribute(gemm_tf32, cudaFuncAttributeMaxDynamicSharedMemorySize, gemmSmem);

    // Fork a side stream for the (independent) decoder chain.
    cudaStream_t s2;
    cudaStreamCreateWithFlags(&s2, cudaStreamNonBlocking);
    cudaEvent_t evF, evJ;
    cudaEventCreateWithFlags(&evF, cudaEventDisableTiming);
    cudaEventCreateWithFlags(&evJ, cudaEventDisableTiming);

    cudaEventRecord(evF, 0);
    cudaStreamWaitEvent(s2, evF, 0);

    // ---- side stream: Xtrg gather -> Gd proj -> decoder recurrence -> Q proj ----
    gather_kernel<<<TDD * NB, 256, 0, s2>>>(trg_ids, embed, Xtrg, TDD);
    cudaMemsetAsync(ctr + 830, 0, 64 * sizeof(int), s2);
    cudaMemsetAsync(Ht2, 0, 2 * 2 * HH * NB * sizeof(float), s2);
    gemm_tf32<<<dim3(CDIV(TDD * NB, 128), CDIV(G3, 128)), 256, gemmSmem, s2>>>(
        Xtrg, Wih_d, bih_d, Gd, TDD * NB, G3, EE, 1, 1);
    gru_persist<<<32, 512, persistSmem, s2>>>(Gd, Gd, Whh_d, Whh_d, bhh_d, bhh_d,
                                              Ht2, ctr + 830, nullptr, Hdec, TDD, 32, 0);
    gemm_tf32<<<dim3(CDIV(TDD * NB, 128), CDIV(HH, 128)), 256, gemmSmem, s2>>>(
        Hdec, Wd, battn, Q, TDD * NB, HH, HH, 0, 0);
    cudaEventRecord(evJ, s2);

    // ---- main stream: encoder chain ----
    gather_kernel<<<SS * NB, 256>>>(src_ids, embed, Xsrc, SS);
    gemm_tf32<<<dim3(CDIV(SS * NB, 128), CDIV(G3, 128)), 256, gemmSmem>>>(
        Xsrc, Wih_f, bih_f, Gf, SS * NB, G3, EE, 1, 1);
    gemm_tf32<<<dim3(CDIV(SS * NB, 128), CDIV(G3, 128)), 256, gemmSmem>>>(
        Xsrc, Wih_b, bih_b, Gb, SS * NB, G3, EE, 1, 1);
    cudaMemsetAsync(ctr, 0, 800 * sizeof(int), 0);
    cudaMemsetAsync(Ht, 0, 2 * 2 * HH * NB * sizeof(float), 0);
    gru_persist<<<64, 512, persistSmem>>>(Gf, Gb, Whh_f, Whh_b, bhh_f, bhh_b,
                                          Ht, ctr, enc, nullptr, SS, 32, 1);
    gemm_tf32<<<dim3(CDIV(NB * SS, 128), CDIV(HH, 128)), 256, gemmSmem>>>(
        enc, Wk, nullptr, KP, NB * SS, HH, 2 * HH, 0, 0);

    // ---- join, then attention + generator head ----
    cudaStreamWaitEvent(0, evJ, 0);
    score_kernel<<<TDD * NB, 256>>>(Q, KP, src_mask, vvec, ATTN);
    ctx_kernel<<<dim3(4, NB), 256>>>(ATTN, enc, CTX);

    concat_kernel<<<TDD * NB, 256>>>(Hdec, CTX, CONC);
    gemm_tf32<<<dim3(CDIV(TDD * NB, 128), CDIV(HH, 128)), 256, gemmSmem>>>(
        CONC, W1, b1, GEN1, TDD * NB, HH, G3, 0, 0);
    gemm_tf32<<<dim3(CDIV(TDD * NB, 128), CDIV(VV, 128)), 256, gemmSmem>>>(
        GEN1, W2, b2, LOG, TDD * NB, VV, HH, 0, 0);
    softmax_kernel<<<TDD * NB, 256>>>(LOG, mxv, invs);

    pgen_kernel<<<(TDD * NB) / 8, 256>>>(Xtrg, CTX, Hdec, Wp, bp, pg);
    outfill_kernel<<<dim3(CDIV(VO, 256), TDD * NB), 256>>>(LOG, pg, mxv, invs, out);
    scatter_kernel<<<TDD * NB, 416>>>(ATTN, pg, ptr_idx, out);
}

// round 16
// speedup vs baseline: 1.1795x; 1.1795x over previous
#include <cuda_runtime.h>
#include <cstdint>

#define NB   32      // batch
#define SS   400     // src len
#define TDD  30      // trg len
#define EE   256     // embed
#define HH   512     // HE == HD == 512
#define G3   1536    // 3*H
#define VV   50000
#define OOVV 50
#define VO   50050

#define CDIV(a,b) (((a)+(b)-1)/(b))

// ---------------- scratch (device globals; no allocations allowed) ----------------
__device__ float g_Xsrc[SS * NB * EE];
__device__ float g_Xtrg[TDD * NB * EE];
__device__ float g_Gf[(size_t)SS * NB * G3];    // transposed: [s][col 1536][n 32]
__device__ float g_Gb[(size_t)SS * NB * G3];
__device__ float g_Gd[(size_t)TDD * NB * G3];
__device__ float g_enc[(size_t)NB * SS * 2 * HH];
__device__ float g_KP[(size_t)NB * SS * HH];
__device__ float g_Ht[2 * 2 * HH * NB];         // encoder h: [parity][dir][k/4][n][4]
__device__ float g_Ht2[2 * 2 * HH * NB];        // decoder h (separate: runs concurrently)
__device__ float g_Hdec[TDD * NB * HH];
__device__ float g_Q[TDD * NB * HH];
__device__ float g_ATTN[TDD * NB * SS];
__device__ float g_CTX[TDD * NB * 2 * HH];
__device__ float g_CONC[TDD * NB * G3];
__device__ float g_GEN1[TDD * NB * HH];
__device__ float g_LOG[(size_t)TDD * NB * VV];
__device__ float g_pg[TDD * NB];
__device__ float g_inv[TDD * NB];
__device__ float g_mx[TDD * NB];
__device__ int   g_ctr[1024];   // enc fwd [0..399], enc bwd [400..799], dec [830..859]

// ---------------- helpers ----------------
__device__ __forceinline__ float fsigmoid(float x) { return 1.f / (1.f + __expf(-x)); }
__device__ __forceinline__ float ftanh(float x) {           // exact-ish (GRU recurrence)
    x = fminf(fmaxf(x, -15.f), 15.f);
    float e2 = __expf(2.f * x);
    return (e2 - 1.f) / (e2 + 1.f);
}
__device__ __forceinline__ float htanh(float x) {           // HW MUFU tanh (attention only)
    float y;
    asm("tanh.approx.f32 %0, %1;" : "=f"(y) : "f"(x));
    return y;
}
__device__ __forceinline__ uint32_t f2tf(float x) {
    uint32_t u;
    asm("cvt.rna.tf32.f32 %0, %1;" : "=r"(u) : "f"(x));
    return u;
}
__device__ __forceinline__ void cpa16(uint32_t dst, const void* src, int sz) {
    asm volatile("cp.async.cg.shared.global [%0], [%1], 16, %2;"
                 :: "r"(dst), "l"(src), "r"(sz) : "memory");
}

// ---------------- embedding gather ------------------------------------------------
__global__ void gather_kernel(const int* __restrict__ ids, const float* __restrict__ embed,
                              float* __restrict__ X, int S)
{
    int row = blockIdx.x;                 // s*32 + n
    int s = row >> 5, n = row & 31;
    int id = ids[n * S + s];
    X[(size_t)row * EE + threadIdx.x] = embed[(size_t)id * EE + threadIdx.x];
}

// ---------------- tf32 tensor-core GEMM v3: cp.async 3-stage ----------------------
__global__ __launch_bounds__(256, 2) void gemm_tf32(
    const float* __restrict__ A, const float* __restrict__ B,
    const float* __restrict__ bias, float* __restrict__ C,
    int M, int N, int K, int transB, int gmode)
{
    extern __shared__ float sm[];        // 3 stages x (A 2560 + B 2560) floats
    const int bm = blockIdx.x * 128;
    const int bn = blockIdx.y * 128;
    const int tid = threadIdx.x;
    const int lane = tid & 31;
    const int warp = tid >> 5;
    const int wm = warp & 1, wn = warp >> 1;
    const uint32_t smBase = (uint32_t)__cvta_generic_to_shared(sm);

    float acc[4][4][4];
#pragma unroll
    for (int mi = 0; mi < 4; mi++)
#pragma unroll
        for (int ni = 0; ni < 4; ni++)
#pragma unroll
            for (int q = 0; q < 4; q++) acc[mi][ni][q] = 0.f;

    const int KT = K >> 4;

    auto issue = [&](int st, int k0) {   // st MUST be a stage index 0..2
        const uint32_t AsU = smBase + (uint32_t)st * 5120u * 4u;
        const uint32_t BsU = AsU + 2560u * 4u;
#pragma unroll
        for (int c = 0; c < 2; c++) {
            int idx = c * 256 + tid;
            int row = idx >> 2, cq = idx & 3;
            const float* src = A + (size_t)(bm + row) * K + k0 + cq * 4;
            int sz = (bm + row < M) ? 16 : 0;
            if (!sz) src = A;
            cpa16(AsU + (uint32_t)(row * 20 + cq * 4) * 4u, src, sz);
        }
        if (!transB) {
#pragma unroll
            for (int c = 0; c < 2; c++) {
                int idx = c * 256 + tid;
                int row = idx >> 5, cq = idx & 31;
                int col = bn + cq * 4;
                const float* src = B + (size_t)(k0 + row) * N + col;
                int rem = N - col;
                int sz = rem >= 4 ? 16 : (rem > 0 ? rem * 4 : 0);
                if (!sz) src = B;
                cpa16(BsU + (uint32_t)(row * 136 + cq * 4) * 4u, src, sz);
            }
        } else {
#pragma unroll
            for (int c = 0; c < 2; c++) {
                int idx = c * 256 + tid;
                int row = idx >> 2, cq = idx & 3;
                const float* src = B + (size_t)(bn + row) * K + k0 + cq * 4;
                int sz = (bn + row < N) ? 16 : 0;
                if (!sz) src = B;
                cpa16(BsU + (uint32_t)(row * 20 + cq * 4) * 4u, src, sz);
            }
        }
        asm volatile("cp.async.commit_group;" ::: "memory");
    };

    issue(0, 0);
    if (KT > 1) issue(1, 16);
    else asm volatile("cp.async.commit_group;" ::: "memory");

    for (int kt = 0; kt < KT; kt++) {
        const int st = kt % 3;
        asm volatile("cp.async.wait_group 1;" ::: "memory");
        __syncthreads();
        const uint32_t* As = reinterpret_cast<const uint32_t*>(sm + st * 5120);
        const uint32_t* Bs = As + 2560;
#pragma unroll
        for (int ks = 0; ks < 2; ks++) {
            uint32_t af[4][4], bf[4][2];
            const int r0 = wm * 64 + (lane >> 2);
            const int c0 = ks * 8 + (lane & 3);
#pragma unroll
            for (int mi = 0; mi < 4; mi++) {
                const int rr = r0 + mi * 16;
                af[mi][0] = As[rr * 20 + c0];
                af[mi][1] = As[(rr + 8) * 20 + c0];
                af[mi][2] = As[rr * 20 + c0 + 4];
                af[mi][3] = As[(rr + 8) * 20 + c0 + 4];
            }
#pragma unroll
            for (int ni = 0; ni < 4; ni++) {
                const int nn = wn * 32 + ni * 8 + (lane >> 2);
                if (transB) {
                    bf[ni][0] = Bs[nn * 20 + c0];
                    bf[ni][1] = Bs[nn * 20 + c0 + 4];
                } else {
                    bf[ni][0] = Bs[c0 * 136 + nn];
                    bf[ni][1] = Bs[(c0 + 4) * 136 + nn];
                }
            }
#pragma unroll
            for (int mi = 0; mi < 4; mi++)
#pragma unroll
                for (int ni = 0; ni < 4; ni++)
                    asm volatile(
                        "mma.sync.aligned.m16n8k8.row.col.f32.tf32.tf32.f32 "
                        "{%0,%1,%2,%3}, {%4,%5,%6,%7}, {%8,%9}, {%0,%1,%2,%3};"
                        : "+f"(acc[mi][ni][0]), "+f"(acc[mi][ni][1]),
                          "+f"(acc[mi][ni][2]), "+f"(acc[mi][ni][3])
                        : "r"(af[mi][0]), "r"(af[mi][1]), "r"(af[mi][2]), "r"(af[mi][3]),
                          "r"(bf[ni][0]), "r"(bf[ni][1]));
        }
        if (kt + 2 < KT) issue((kt + 2) % 3, (kt + 2) << 4);
        else asm volatile("cp.async.commit_group;" ::: "memory");
    }

#pragma unroll
    for (int mi = 0; mi < 4; mi++) {
#pragma unroll
        for (int ni = 0; ni < 4; ni++) {
            const int row = bm + wm * 64 + mi * 16 + (lane >> 2);
            const int col = bn + wn * 32 + ni * 8 + (lane & 3) * 2;
#pragma unroll
            for (int h = 0; h < 2; h++) {
                const int m = row + h * 8;
                if (m < M) {
#pragma unroll
                    for (int q = 0; q < 2; q++) {
                        const int n = col + q;
                        if (n < N) {
                            float v = acc[mi][ni][h * 2 + q];
                            if (bias) v += __ldg(&bias[n]);
                            if (gmode) C[((size_t)(m >> 5) * N + n) * 32 + (m & 31)] = v;
                            else       C[(size_t)m * N + n] = v;
                        }
                    }
                }
            }
        }
    }
}

// ---------------- persistent GRU recurrence (tensor-core, 512 threads) ------------
// R14 shape (proven best): 64 CTAs/dir, 8 units/CTA (24 gate-rows padded to 32),
// 16 warps split K=512; gate phase on warps 0..7; per-dir grid barrier (64 arrivals).
__global__ __launch_bounds__(512, 1) void gru_persist(
    const float* __restrict__ G0T, const float* __restrict__ G1T,
    const float* __restrict__ Whh0, const float* __restrict__ Whh1,
    const float* __restrict__ bhh0, const float* __restrict__ bhh1,
    float* __restrict__ Ht, int* ctr,
    float* __restrict__ encOut, float* __restrict__ hdecOut,
    int nSteps, int nCTA, int encMode)
{
    extern __shared__ uint32_t smemU[];
    uint32_t* AF = smemU;                              // [16 warps][8 (mi*4+ki)][32 lanes][4]
    float* rs = reinterpret_cast<float*>(smemU + 16 * 8 * 32 * 4);  // [16*32 rows][33]

    const int dir   = encMode ? (blockIdx.x >> 6) : 0;
    const int utile = blockIdx.x & 63;
    const int u0 = utile * 8;
    const float* Whh = dir ? Whh1 : Whh0;
    const float* bhh = dir ? bhh1 : bhh0;
    const float* GT  = dir ? G1T  : G0T;

    const int tid = threadIdx.x, lane = tid & 31, wk = tid >> 5;   // wk 0..15

#pragma unroll
    for (int mi = 0; mi < 2; mi++)
#pragma unroll
        for (int ki = 0; ki < 4; ki++)
#pragma unroll
            for (int r = 0; r < 4; r++) {
                int row = mi * 16 + (lane >> 2) + (r & 1) * 8;           // gate-row c
                int col = wk * 32 + ki * 8 + (lane & 3) + (r >> 1) * 4;  // k
                float v = 0.f;
                if (row < 24)
                    v = Whh[((size_t)((row >> 3) * 512 + u0 + (row & 7))) * 512 + col];
                AF[((wk * 8 + mi * 4 + ki) * 32 + lane) * 4 + r] = f2tf(v);
            }
    float b_r = 0.f, b_z = 0.f, b_n = 0.f;
    const int u = u0 + wk;               // valid for wk < 8
    if (wk < 8) {
        b_r = bhh[u];
        b_z = bhh[512 + u];
        b_n = bhh[1024 + u];
    }
    __syncthreads();

    float hprev = 0.f;

    for (int t = 0; t < nSteps; t++) {
        const int p = t & 1;
        const float* Hp = Ht + ((size_t)p * 2 + dir) * HH * NB;
        float*       Hn = Ht + ((size_t)(1 - p) * 2 + dir) * HH * NB;
        const int gidx = dir ? (nSteps - 1 - t) : t;
        const float* Gt = GT + (size_t)gidx * G3 * NB;

        float gir = 0.f, giz = 0.f, gin = 0.f;
        if (wk < 8) {
            gir = __ldg(&Gt[u * 32 + lane]);
            giz = __ldg(&Gt[(512 + u) * 32 + lane]);
            gin = __ldg(&Gt[(1024 + u) * 32 + lane]);
        }

        uint32_t bReg[4][4][2];          // [ni][ki][2]
        const int kq = wk * 8;
#pragma unroll
        for (int ki = 0; ki < 4; ki++)
#pragma unroll
            for (int ni = 0; ni < 4; ni++) {
                float v0 = __ldcg(&Hp[(kq + ki * 2) * 128 + ni * 32 + lane]);
                float v1 = __ldcg(&Hp[(kq + ki * 2 + 1) * 128 + ni * 32 + lane]);
                bReg[ni][ki][0] = f2tf(v0);
                bReg[ni][ki][1] = f2tf(v1);
            }

        float acc[2][4][4];
#pragma unroll
        for (int mi = 0; mi < 2; mi++)
#pragma unroll
            for (int ni = 0; ni < 4; ni++)
#pragma unroll
                for (int q = 0; q < 4; q++) acc[mi][ni][q] = 0.f;

#pragma unroll
        for (int mi = 0; mi < 2; mi++)
#pragma unroll
            for (int ki = 0; ki < 4; ki++) {
                uint4 a = *reinterpret_cast<const uint4*>(
                    &AF[((wk * 8 + mi * 4 + ki) * 32 + lane) * 4]);
#pragma unroll
                for (int ni = 0; ni < 4; ni++)
                    asm volatile(
                        "mma.sync.aligned.m16n8k8.row.col.f32.tf32.tf32.f32 "
                        "{%0,%1,%2,%3}, {%4,%5,%6,%7}, {%8,%9}, {%0,%1,%2,%3};"
                        : "+f"(acc[mi][ni][0]), "+f"(acc[mi][ni][1]),
                          "+f"(acc[mi][ni][2]), "+f"(acc[mi][ni][3])
                        : "r"(a.x), "r"(a.y), "r"(a.z), "r"(a.w),
                          "r"(bReg[ni][ki][0]), "r"(bReg[ni][ki][1]));
            }

        {
            const int row0 = lane >> 2, col0 = 2 * (lane & 3);
#pragma unroll
            for (int mi = 0; mi < 2; mi++)
#pragma unroll
                for (int ni = 0; ni < 4; ni++) {
                    float* base = &rs[(wk * 32 + mi * 16 + row0) * 33 + ni * 8 + col0];
                    base[0]          = acc[mi][ni][0];
                    base[1]          = acc[mi][ni][1];
                    base[33 * 8]     = acc[mi][ni][2];
                    base[33 * 8 + 1] = acc[mi][ni][3];
                }
        }
        __syncthreads();

        if (wk < 8) {
            float ar = 0.f, az = 0.f, an = 0.f;
#pragma unroll
            for (int w2 = 0; w2 < 16; w2++) {
                ar += rs[(w2 * 32 + wk) * 33 + lane];
                az += rs[(w2 * 32 + 8 + wk) * 33 + lane];
                an += rs[(w2 * 32 + 16 + wk) * 33 + lane];
            }
            float r = fsigmoid(gir + ar + b_r);
            float z = fsigmoid(giz + az + b_z);
            float nn = ftanh(gin + (an + b_n) * r);
            float hnew = (1.f - z) * nn + z * hprev;
            hprev = hnew;
            __stcg(&Hn[(u >> 2) * 128 + lane * 4 + (u & 3)], hnew);
            if (encMode) {
                int s = dir ? (nSteps - 1 - t) : t;
                encOut[(size_t)lane * SS * 1024 + (size_t)s * 1024 + dir * 512 + u] = hnew;
            } else {
                hdecOut[(size_t)t * NB * HH + (size_t)lane * HH + u] = hnew;
            }
        }
        __syncthreads();

        if (t + 1 < nSteps) {
            if (tid == 0) {
                int* a = &ctr[dir ? (nSteps + t) : t];
                asm volatile("red.release.gpu.global.add.u32 [%0], 1;" :: "l"(a) : "memory");
                unsigned v;
                do {
                    asm volatile("ld.acquire.gpu.global.u32 %0, [%1];" : "=r"(v) : "l"(a) : "memory");
                } while (v < (unsigned)nCTA);
            }
            __syncthreads();
        }
    }
}

// ---------------- attention scores + softmax (one CTA per (t,n) row) --------------
__global__ void score_kernel(const float* __restrict__ Q, const float* __restrict__ KP,
                             const float* __restrict__ mask, const float* __restrict__ vvec,
                             float* __restrict__ ATTN)
{
    const int row = blockIdx.x;          // t*32 + n
    const int n = row & 31;
    const int tid = threadIdx.x, lane = tid & 31, warp = tid >> 5;
    __shared__ float qs[HH], vs[HH], es[SS], red[256];

    for (int i = tid; i < HH; i += 256) { qs[i] = Q[(size_t)row * HH + i]; vs[i] = vvec[i]; }
    __syncthreads();

    for (int s = warp; s < SS; s += 8) {
        const float* kp = KP + ((size_t)n * SS + s) * HH;
        float part = 0.f;
        for (int d = lane; d < HH; d += 32)
            part += htanh(kp[d] + qs[d]) * vs[d];
#pragma unroll
        for (int o = 16; o; o >>= 1) part += __shfl_xor_sync(0xffffffffu, part, o);
        if (lane == 0) es[s] = part + (1.f - mask[n * SS + s]) * (-1e10f);
    }
    __syncthreads();

    float m = -1e30f;
    for (int s = tid; s < SS; s += 256) m = fmaxf(m, es[s]);
    red[tid] = m; __syncthreads();
    for (int st = 128; st; st >>= 1) { if (tid < st) red[tid] = fmaxf(red[tid], red[tid + st]); __syncthreads(); }
    float mx = red[0]; __syncthreads();

    float sum = 0.f;
    for (int s = tid; s < SS; s += 256) { float e = __expf(es[s] - mx); es[s] = e; sum += e; }
    red[tid] = sum; __syncthreads();
    for (int st = 128; st; st >>= 1) { if (tid < st) red[tid] += red[tid + st]; __syncthreads(); }
    float inv = 1.f / red[0]; __syncthreads();

    for (int s = tid; s < SS; s += 256)
        ATTN[(size_t)row * SS + s] = es[s] * inv;
}

// ---------------- context: CTX[t,n,:] = sum_s ATTN[t,n,s] * enc[n,s,:] ------------
__global__ __launch_bounds__(256) void ctx_kernel(
    const float* __restrict__ ATTN, const float* __restrict__ ENC,
    float* __restrict__ CTX)
{
    const int n = blockIdx.y;
    const int d = blockIdx.x * 256 + threadIdx.x;
    const int tid = threadIdx.x;
    __shared__ float at[TDD][129];

    float acc[TDD];
#pragma unroll
    for (int t = 0; t < TDD; t++) acc[t] = 0.f;

    for (int s0 = 0; s0 < SS; s0 += 128) {
        __syncthreads();
        for (int idx = tid; idx < TDD * 128; idx += 256) {
            int t = idx >> 7, si = idx & 127;
            at[t][si] = (s0 + si < SS) ? ATTN[((size_t)(t * NB + n)) * SS + s0 + si] : 0.f;
        }
        __syncthreads();
        const int lim = min(128, SS - s0);
        for (int si = 0; si < lim; si++) {
            float e = __ldg(&ENC[((size_t)n * SS + s0 + si) * 1024 + d]);
#pragma unroll
            for (int t = 0; t < TDD; t++) acc[t] = fmaf(at[t][si], e, acc[t]);
        }
    }
#pragma unroll
    for (int t = 0; t < TDD; t++)
        CTX[((size_t)(t * NB + n)) * 1024 + d] = acc[t];
}

// ---------------- concat [h, ctx] --------------------------------------------------
__global__ void concat_kernel(const float* __restrict__ H, const float* __restrict__ CTX,
                              float* __restrict__ C)
{
    int row = blockIdx.x;
    for (int i = threadIdx.x; i < G3; i += 256)
        C[(size_t)row * G3 + i] = (i < HH) ? H[(size_t)row * HH + i]
                                           : CTX[(size_t)row * 1024 + (i - HH)];
}

// ---------------- row softmax stats over V: mx + 1/sum (no exp write) -------------
__global__ void softmax_kernel(const float* __restrict__ LOG, float* __restrict__ mxv,
                               float* __restrict__ invs)
{
    const int row = blockIdx.x, tid = threadIdx.x;
    const float* p = LOG + (size_t)row * VV;
    __shared__ float red[256];
    float m = -1e30f;
    for (int i = tid; i < VV; i += 256) m = fmaxf(m, p[i]);
    red[tid] = m; __syncthreads();
    for (int st = 128; st; st >>= 1) { if (tid < st) red[tid] = fmaxf(red[tid], red[tid + st]); __syncthreads(); }
    float mx = red[0]; __syncthreads();
    float sum = 0.f;
    for (int i = tid; i < VV; i += 256) sum += __expf(p[i] - mx);
    red[tid] = sum; __syncthreads();
    for (int st = 128; st; st >>= 1) { if (tid < st) red[tid] += red[tid + st]; __syncthreads(); }
    if (tid == 0) { mxv[row] = mx; invs[row] = 1.f / red[0]; }
}

// ---------------- p_gen = sigmoid([xi, ctx, h] @ Wp + bp) -------------------------
__global__ void pgen_kernel(const float* __restrict__ Xtrg, const float* __restrict__ CTX,
                            const float* __restrict__ H, const float* __restrict__ Wp,
                            const float* __restrict__ bp, float* __restrict__ pg)
{
    const int warp = threadIdx.x >> 5, lane = threadIdx.x & 31;
    const int row = blockIdx.x * 8 + warp;
    float part = 0.f;
    for (int k = lane; k < 1792; k += 32) {
        float xv;
        if (k < 256)       xv = Xtrg[(size_t)row * EE + k];
        else if (k < 1280) xv = CTX[(size_t)row * 1024 + (k - 256)];
        else               xv = H[(size_t)row * HH + (k - 1280)];
        part += xv * Wp[k];
    }
#pragma unroll
    for (int o = 16; o; o >>= 1) part += __shfl_xor_sync(0xffffffffu, part, o);
    if (lane == 0) pg[row] = fsigmoid(part + bp[0]);
}

// ---------------- out = p_gen * softmax(LOG) (exp recomputed; OOV zeroed) ---------
__global__ void outfill_kernel(const float* __restrict__ LOG, const float* __restrict__ pg,
                               const float* __restrict__ mxv, const float* __restrict__ invs,
                               float* __restrict__ out)
{
    const int row = blockIdx.y;          // t*32 + n
    const int t = row / NB, n = row % NB;
    const int vv = blockIdx.x * 256 + threadIdx.x;
    if (vv >= VO) return;
    float val = 0.f;
    if (vv < VV)
        val = pg[row] * invs[row] * __expf(LOG[(size_t)row * VV + vv] - mxv[row]);
    out[((size_t)n * TDD + t) * VO + vv] = val;
}

// ---------------- deterministic scatter-add of (1-p)*attn at ptr indices ----------
__global__ void scatter_kernel(const float* __restrict__ ATTN, const float* __restrict__ pg,
                               const int* __restrict__ ptr_idx, float* __restrict__ out)
{
    const int row = blockIdx.x;          // t*32 + n
    const int t = row / NB, n = row % NB;
    __shared__ int   sidx[SS];
    __shared__ float sw[SS];
    const int s = threadIdx.x;
    const float om = 1.f - pg[row];
    if (s < SS) {
        sidx[s] = ptr_idx[n * SS + s];
        sw[s]   = om * ATTN[(size_t)row * SS + s];
    }
    __syncthreads();
    if (s < SS) {
        int my = sidx[s];
        bool first = true;
        for (int s2 = 0; s2 < s; s2++) if (sidx[s2] == my) { first = false; break; }
        if (first) {
            float val = sw[s];
            for (int s2 = s + 1; s2 < SS; s2++) if (sidx[s2] == my) val += sw[s2];
            out[((size_t)n * TDD + t) * VO + my] += val;   // rows exclusive -> no atomics
        }
    }
}

// ---------------- launch --------------------------------------------------------
extern "C" void kernel_launch(void* const* d_in, const int* in_sizes, int n_in,
                              void* d_out, int out_size)
{
    const int*   src_ids  = (const int*)  d_in[0];
    const float* src_mask = (const float*)d_in[1];
    const int*   trg_ids  = (const int*)  d_in[2];
    const int*   ptr_idx  = (const int*)  d_in[3];
    const float* embed    = (const float*)d_in[4];
    const float* Wih_f = (const float*)d_in[5],  *Whh_f = (const float*)d_in[6];
    const float* bih_f = (const float*)d_in[7],  *bhh_f = (const float*)d_in[8];
    const float* Wih_b = (const float*)d_in[9],  *Whh_b = (const float*)d_in[10];
    const float* bih_b = (const float*)d_in[11], *bhh_b = (const float*)d_in[12];
    const float* Wih_d = (const float*)d_in[13], *Whh_d = (const float*)d_in[14];
    const float* bih_d = (const float*)d_in[15], *bhh_d = (const float*)d_in[16];
    const float* Wk    = (const float*)d_in[17], *Wd    = (const float*)d_in[18];
    const float* battn = (const float*)d_in[19], *vvec  = (const float*)d_in[20];
    const float* W1    = (const float*)d_in[21], *b1    = (const float*)d_in[22];
    const float* W2    = (const float*)d_in[23], *b2    = (const float*)d_in[24];
    const float* Wp    = (const float*)d_in[25], *bp    = (const float*)d_in[26];
    float* out = (float*)d_out;

    float *Xsrc, *Xtrg, *Gf, *Gb, *Gd, *enc, *KP, *Ht, *Ht2, *Hdec, *Q, *ATTN, *CTX,
          *CONC, *GEN1, *LOG, *pg, *invs, *mxv;
    int* ctr;
    cudaGetSymbolAddress((void**)&Xsrc, g_Xsrc);
    cudaGetSymbolAddress((void**)&Xtrg, g_Xtrg);
    cudaGetSymbolAddress((void**)&Gf,   g_Gf);
    cudaGetSymbolAddress((void**)&Gb,   g_Gb);
    cudaGetSymbolAddress((void**)&Gd,   g_Gd);
    cudaGetSymbolAddress((void**)&enc,  g_enc);
    cudaGetSymbolAddress((void**)&KP,   g_KP);
    cudaGetSymbolAddress((void**)&Ht,   g_Ht);
    cudaGetSymbolAddress((void**)&Ht2,  g_Ht2);
    cudaGetSymbolAddress((void**)&Hdec, g_Hdec);
    cudaGetSymbolAddress((void**)&Q,    g_Q);
    cudaGetSymbolAddress((void**)&ATTN, g_ATTN);
    cudaGetSymbolAddress((void**)&CTX,  g_CTX);
    cudaGetSymbolAddress((void**)&CONC, g_CONC);
    cudaGetSymbolAddress((void**)&GEN1, g_GEN1);
    cudaGetSymbolAddress((void**)&LOG,  g_LOG);
    cudaGetSymbolAddress((void**)&pg,   g_pg);
    cudaGetSymbolAddress((void**)&invs, g_inv);
    cudaGetSymbolAddress((void**)&mxv,  g_mx);
    cudaGetSymbolAddress((void**)&ctr,  g_ctr);

    // gru (R14 shape): AF 16*8*32*4 u32 (64KB) + rs 16*32*33 f32 (66KB)
    const int persistSmem = (16 * 8 * 32 * 4) * 4 + (16 * 32 * 33) * 4;
    cudaFuncSetAttribute(gru_persist, cudaFuncAttributeMaxDynamicSharedMemorySize, persistSmem);
    const int gemmSmem = 3 * 5120 * 4;
    cudaFuncSetAttribute(gemm_tf32, cudaFuncAttributeMaxDynamicSharedMemorySize, gemmSmem);

    // Fork a side stream for the (independent) decoder chain.
    cudaStream_t s2;
    cudaStreamCreateWithFlags(&s2, cudaStreamNonBlocking);
    cudaEvent_t evF, evJ;
    cudaEventCreateWithFlags(&evF, cudaEventDisableTiming);
    cudaEventCreateWithFlags(&evJ, cudaEventDisableTiming);

    cudaEventRecord(evF, 0);
    cudaStreamWaitEvent(s2, evF, 0);

    // ---- side stream: Xtrg gather -> Gd proj -> decoder recurrence -> Q proj ----
    gather_kernel<<<TDD * NB, 256, 0, s2>>>(trg_ids, embed, Xtrg, TDD);
    cudaMemsetAsync(ctr + 830, 0, 64 * sizeof(int), s2);
    cudaMemsetAsync(Ht2, 0, 2 * 2 * HH * NB * sizeof(float), s2);
    gemm_tf32<<<dim3(CDIV(TDD * NB, 128), CDIV(G3, 128)), 256, gemmSmem, s2>>>(
        Xtrg, Wih_d, bih_d, Gd, TDD * NB, G3, EE, 1, 1);
    gru_persist<<<64, 512, persistSmem, s2>>>(Gd, Gd, Whh_d, Whh_d, bhh_d, bhh_d,
                                              Ht2, ctr + 830, nullptr, Hdec, TDD, 64, 0);
    gemm_tf32<<<dim3(CDIV(TDD * NB, 128), CDIV(HH, 128)), 256, gemmSmem, s2>>>(
        Hdec, Wd, battn, Q, TDD * NB, HH, HH, 0, 0);
    cudaEventRecord(evJ, s2);

    // ---- main stream: encoder chain ----
    gather_kernel<<<SS * NB, 256>>>(src_ids, embed, Xsrc, SS);
    gemm_tf32<<<dim3(CDIV(SS * NB, 128), CDIV(G3, 128)), 256, gemmSmem>>>(
        Xsrc, Wih_f, bih_f, Gf, SS * NB, G3, EE, 1, 1);
    gemm_tf32<<<dim3(CDIV(SS * NB, 128), CDIV(G3, 128)), 256, gemmSmem>>>(
        Xsrc, Wih_b, bih_b, Gb, SS * NB, G3, EE, 1, 1);
    cudaMemsetAsync(ctr, 0, 800 * sizeof(int), 0);
    cudaMemsetAsync(Ht, 0, 2 * 2 * HH * NB * sizeof(float), 0);
    gru_persist<<<128, 512, persistSmem>>>(Gf, Gb, Whh_f, Whh_b, bhh_f, bhh_b,
                                           Ht, ctr, enc, nullptr, SS, 64, 1);
    gemm_tf32<<<dim3(CDIV(NB * SS, 128), CDIV(HH, 128)), 256, gemmSmem>>>(
        enc, Wk, nullptr, KP, NB * SS, HH, 2 * HH, 0, 0);

    // ---- join, then attention + generator head ----
    cudaStreamWaitEvent(0, evJ, 0);
    score_kernel<<<TDD * NB, 256>>>(Q, KP, src_mask, vvec, ATTN);
    ctx_kernel<<<dim3(4, NB), 256>>>(ATTN, enc, CTX);

    concat_kernel<<<TDD * NB, 256>>>(Hdec, CTX, CONC);
    gemm_tf32<<<dim3(CDIV(TDD * NB, 128), CDIV(HH, 128)), 256, gemmSmem>>>(
        CONC, W1, b1, GEN1, TDD * NB, HH, G3, 0, 0);
    gemm_tf32<<<dim3(CDIV(TDD * NB, 128), CDIV(VV, 128)), 256, gemmSmem>>>(
        GEN1, W2, b2, LOG, TDD * NB, VV, HH, 0, 0);
    softmax_kernel<<<TDD * NB, 256>>>(LOG, mxv, invs);

    pgen_kernel<<<(TDD * NB) / 8, 256>>>(Xtrg, CTX, Hdec, Wp, bp, pg);
    outfill_kernel<<<dim3(CDIV(VO, 256), TDD * NB), 256>>>(LOG, pg, mxv, invs, out);
    scatter_kernel<<<TDD * NB, 416>>>(ATTN, pg, ptr_idx, out);
}